// round 11
// baseline (speedup 1.0000x reference)
#include <cuda_runtime.h>
#include <cuda_bf16.h>
#include <cstdint>

#define B_   8
#define N_   4096
#define E_   2048
#define C_   128
#define EPS_ 1e-6f

#define KT   64
#define STAGE_BYTES 65536
#define NSTAGE 3
#define A_HI 0
#define A_LO 16384
#define B_HI 32768
#define B_LO 49152
#define TILE0 1024
#define DSMEM (1024 + 1024 + NSTAGE * STAGE_BYTES)

#define SW(o) ((o) ^ ((((uint32_t)(o)) >> 3) & 0x70u))

// ---------------- static device scratch ----------------
__device__ float g_dv[B_ * N_];
__device__ float g_de_part[B_ * 8 * E_];
__device__ __nv_bfloat16 g_H_hi[(size_t)B_ * N_ * E_];
__device__ __nv_bfloat16 g_H_lo[(size_t)B_ * N_ * E_];
__device__ __nv_bfloat16 g_xt_hi[(size_t)B_ * C_ * N_];
__device__ __nv_bfloat16 g_xt_lo[(size_t)B_ * C_ * N_];
__device__ __nv_bfloat16 g_W_hi[C_ * C_];
__device__ __nv_bfloat16 g_W_lo[C_ * C_];
__device__ __nv_bfloat16 g_Mt_hi[(size_t)B_ * C_ * E_];
__device__ __nv_bfloat16 g_Mt_lo[(size_t)B_ * C_ * E_];
__device__ __nv_bfloat16 g_o2_hi[(size_t)B_ * N_ * C_];
__device__ __nv_bfloat16 g_o2_lo[(size_t)B_ * N_ * C_];

// ---------------- helpers ----------------
__device__ __forceinline__ uint32_t s2u(const void* p) {
    uint32_t a;
    asm("{ .reg .u64 t; cvta.to.shared.u64 t, %1; cvt.u32.u64 %0, t; }" : "=r"(a) : "l"(p));
    return a;
}
__device__ __forceinline__ void cpa16(uint32_t dst, const void* src) {
    asm volatile("cp.async.cg.shared.global [%0], [%1], 16;" :: "r"(dst), "l"(src));
}
#define CP_COMMIT() asm volatile("cp.async.commit_group;" ::: "memory")
#define CP_WAIT0()  asm volatile("cp.async.wait_group 0;" ::: "memory")
#define CP_WAIT1()  asm volatile("cp.async.wait_group 1;" ::: "memory")

__device__ __forceinline__ void ldsm4(uint32_t r[4], uint32_t addr) {
    asm volatile("ldmatrix.sync.aligned.m8n8.x4.shared.b16 {%0,%1,%2,%3}, [%4];"
        : "=r"(r[0]), "=r"(r[1]), "=r"(r[2]), "=r"(r[3]) : "r"(addr));
}
__device__ __forceinline__ void ldsm4t(uint32_t r[4], uint32_t addr) {
    asm volatile("ldmatrix.sync.aligned.m8n8.x4.trans.shared.b16 {%0,%1,%2,%3}, [%4];"
        : "=r"(r[0]), "=r"(r[1]), "=r"(r[2]), "=r"(r[3]) : "r"(addr));
}
__device__ __forceinline__ void mma16816(float c[4], const uint32_t a[4], uint32_t b0, uint32_t b1) {
    asm volatile("mma.sync.aligned.m16n8k16.row.col.f32.bf16.bf16.f32 "
        "{%0,%1,%2,%3}, {%4,%5,%6,%7}, {%8,%9}, {%0,%1,%2,%3};"
        : "+f"(c[0]), "+f"(c[1]), "+f"(c[2]), "+f"(c[3])
        : "r"(a[0]), "r"(a[1]), "r"(a[2]), "r"(a[3]), "r"(b0), "r"(b1));
}
__device__ __forceinline__ void split2(float f0, float f1, uint32_t& h, uint32_t& l) {
    unsigned short h0 = __bfloat16_as_ushort(__float2bfloat16(f0));
    unsigned short h1 = __bfloat16_as_ushort(__float2bfloat16(f1));
    float r0 = f0 - __bfloat162float(__ushort_as_bfloat16(h0));
    float r1 = f1 - __bfloat162float(__ushort_as_bfloat16(h1));
    unsigned short l0 = __bfloat16_as_ushort(__float2bfloat16(r0));
    unsigned short l1 = __bfloat16_as_ushort(__float2bfloat16(r1));
    h = (uint32_t)h0 | ((uint32_t)h1 << 16);
    l = (uint32_t)l0 | ((uint32_t)l1 << 16);
}

// ---------------- H split + Dv in ONE streaming pass over H ----------------
__global__ void hsplit_dv_kernel(const float* __restrict__ H) {
    int row = blockIdx.x;  // b*N + n
    int t = threadIdx.x;
    const float4* p = (const float4*)(H + (size_t)row * E_);
    __nv_bfloat16* hh = g_H_hi + (size_t)row * E_;
    __nv_bfloat16* hl = g_H_lo + (size_t)row * E_;
    float s = 0.f;
#pragma unroll
    for (int i = 0; i < 4; i++) {
        int e4 = t + i * 128;
        float4 v = p[e4];
        s += (v.x + v.y) + (v.z + v.w);
        uint32_t h01, l01, h23, l23;
        split2(v.x, v.y, h01, l01);
        split2(v.z, v.w, h23, l23);
        *(uint2*)(hh + e4 * 4) = make_uint2(h01, h23);
        *(uint2*)(hl + e4 * 4) = make_uint2(l01, l23);
    }
    __shared__ float red[4];
#pragma unroll
    for (int o = 16; o > 0; o >>= 1) s += __shfl_down_sync(0xffffffffu, s, o);
    if ((t & 31) == 0) red[t >> 5] = s;
    __syncthreads();
    if (t == 0) g_dv[row] = rsqrtf(red[0] + red[1] + red[2] + red[3] + EPS_);
}

// ---------------- De partial sums ----------------
__global__ void de_part_kernel(const float* __restrict__ H) {
    int e = blockIdx.x * 256 + threadIdx.x;
    int chunk = blockIdx.y, b = blockIdx.z;
    const float* p = H + ((size_t)b * N_ + (size_t)chunk * 512) * E_ + e;
    float s0 = 0.f, s1 = 0.f, s2 = 0.f, s3 = 0.f;
#pragma unroll 4
    for (int n = 0; n < 512; n += 4) {
        s0 += p[(size_t)(n + 0) * E_];
        s1 += p[(size_t)(n + 1) * E_];
        s2 += p[(size_t)(n + 2) * E_];
        s3 += p[(size_t)(n + 3) * E_];
    }
    g_de_part[((b * 8) + chunk) * E_ + e] = (s0 + s1) + (s2 + s3);
}

// xt[b][c][n] = split( x[b][n][c] * dv[b][n] )
__global__ void xt_kernel(const float* __restrict__ x) {
    __shared__ float t[32][33];
    int b = blockIdx.z, n0 = blockIdx.x * 32, c0 = blockIdx.y * 32;
    int tx = threadIdx.x, ty = threadIdx.y;
#pragma unroll
    for (int i = 0; i < 4; i++) {
        int n = n0 + ty + i * 8;
        t[ty + i * 8][tx] = x[((size_t)(b * N_ + n)) * C_ + c0 + tx] * g_dv[b * N_ + n];
    }
    __syncthreads();
#pragma unroll
    for (int i = 0; i < 4; i++) {
        int c = c0 + ty + i * 8;
        float f = t[tx][ty + i * 8];
        __nv_bfloat16 h = __float2bfloat16(f);
        __nv_bfloat16 l = __float2bfloat16(f - __bfloat162float(h));
        size_t o = ((size_t)(b * C_ + c)) * N_ + n0 + tx;
        g_xt_hi[o] = h;
        g_xt_lo[o] = l;
    }
}

__global__ void wsplit_kernel(const float* __restrict__ W) {
    int i = blockIdx.x * 256 + threadIdx.x;
    float f = W[i];
    __nv_bfloat16 h = __float2bfloat16(f);
    g_W_hi[i] = h;
    g_W_lo[i] = __float2bfloat16(f - __bfloat162float(h));
}

// ---------------- templated HMMA GEMM, 3-stage cp.async pipeline ----------------
// MODE 0: Mt[c, e]  = (xt . H) * De^-1[e]   A=xt K-major, B=H natural + ldsm.trans  grid(16,8)
// MODE 1: o2[n, c]  = (H . Mt) * dv[n]      A=H K-major,  B=Mt K-major              grid(32,8)
// MODE 2: out[r, c] = (o2 . W) + bias[c]                                            grid(256)
template<int MODE>
__global__ __launch_bounds__(256) void gemm_tc(const float* __restrict__ bias,
                                               float* __restrict__ outp) {
    constexpr int NK = (MODE == 0) ? N_ / KT : ((MODE == 1) ? E_ / KT : C_ / KT);
    extern __shared__ char smem[];
    uint32_t raw = s2u(smem);
    uint32_t sb = (raw + 1023u) & ~1023u;
    float* scS = (float*)(smem + (sb - raw));
    const int tid = threadIdx.x;
    const int lane = tid & 31, wid = tid >> 5;
    const int warp_m = wid >> 2, warp_n = wid & 3;
    const int m0 = blockIdx.x * 128;
    const int b = (MODE == 2) ? 0 : blockIdx.y;

    if (tid < 128) {
        if (MODE == 0) {
            float s = 0.f;
#pragma unroll
            for (int c = 0; c < 8; c++) s += g_de_part[(b * 8 + c) * E_ + m0 + tid];
            scS[tid] = 1.0f / (s + EPS_);
        }
        if (MODE == 1) scS[tid] = g_dv[b * N_ + m0 + tid];
        if (MODE == 2) scS[tid] = bias[tid];
    }

    const __nv_bfloat16* xh = g_xt_hi + (size_t)b * C_ * N_;
    const __nv_bfloat16* xl = g_xt_lo + (size_t)b * C_ * N_;
    const __nv_bfloat16* Hh = g_H_hi + (size_t)b * N_ * E_;
    const __nv_bfloat16* Hl = g_H_lo + (size_t)b * N_ * E_;
    const __nv_bfloat16* mh = g_Mt_hi + (size_t)b * C_ * E_;
    const __nv_bfloat16* ml = g_Mt_lo + (size_t)b * C_ * E_;

    auto fill = [&](int s, int kt) {
        uint32_t base = sb + TILE0 + s * STAGE_BYTES;
        int koff = kt * KT;
        if constexpr (MODE == 0) {
#pragma unroll
            for (int i = 0; i < 4; i++) {
                int idx = tid + i * 256, row = idx >> 3, q = idx & 7;
                uint32_t off = SW(row * 128 + q * 16);
                cpa16(base + A_HI + off, xh + (size_t)row * N_ + koff + q * 8);
                cpa16(base + A_LO + off, xl + (size_t)row * N_ + koff + q * 8);
            }
#pragma unroll
            for (int i = 0; i < 4; i++) {
                int idx = tid + i * 256, row = idx >> 4, c = idx & 15;
                uint32_t off = row * 256 + ((uint32_t)(c ^ (row & 15)) << 4);
                cpa16(base + B_HI + off, Hh + (size_t)(koff + row) * E_ + m0 + c * 8);
                cpa16(base + B_LO + off, Hl + (size_t)(koff + row) * E_ + m0 + c * 8);
            }
        } else if constexpr (MODE == 1) {
#pragma unroll
            for (int i = 0; i < 4; i++) {
                int idx = tid + i * 256, row = idx >> 3, q = idx & 7;
                uint32_t off = SW(row * 128 + q * 16);
                cpa16(base + A_HI + off, Hh + (size_t)(m0 + row) * E_ + koff + q * 8);
                cpa16(base + A_LO + off, Hl + (size_t)(m0 + row) * E_ + koff + q * 8);
                cpa16(base + B_HI + off, mh + (size_t)row * E_ + koff + q * 8);
                cpa16(base + B_LO + off, ml + (size_t)row * E_ + koff + q * 8);
            }
        } else {
#pragma unroll
            for (int i = 0; i < 4; i++) {
                int idx = tid + i * 256, row = idx >> 3, q = idx & 7;
                uint32_t off = SW(row * 128 + q * 16);
                cpa16(base + A_HI + off, g_o2_hi + (size_t)(m0 + row) * C_ + koff + q * 8);
                cpa16(base + A_LO + off, g_o2_lo + (size_t)(m0 + row) * C_ + koff + q * 8);
                cpa16(base + B_HI + off, g_W_hi + (size_t)row * C_ + koff + q * 8);
                cpa16(base + B_LO + off, g_W_lo + (size_t)row * C_ + koff + q * 8);
            }
        }
    };

    float acc[4][4][4];
#pragma unroll
    for (int i = 0; i < 4; i++)
#pragma unroll
        for (int j = 0; j < 4; j++)
#pragma unroll
            for (int k = 0; k < 4; k++) acc[i][j][k] = 0.f;

    const int a_row = warp_m * 64 + (lane & 15);
    const int a_kb  = (lane >> 4) * 16;
    const int b_row = warp_n * 32 + (lane & 7) + ((lane >> 4) << 3);
    const int b_kb  = ((lane >> 3) & 1) * 16;
    const uint32_t tb_row_lo = ((lane >> 3) & 1) * 8 + (lane & 7);
    const uint32_t tb_cadd   = lane >> 4;

    // 3-stage prologue: tiles 0 and 1 in flight before first consume
    fill(0, 0);
    CP_COMMIT();
    if (NK > 1) { fill(1, 1); CP_COMMIT(); }

    int stage = 0;
    for (int kt = 0; kt < NK; kt++) {
        // steady state: allow the next tile's group to stay in flight
        if (kt + 1 < NK) CP_WAIT1(); else CP_WAIT0();
        __syncthreads();

        uint32_t base = sb + TILE0 + stage * STAGE_BYTES;
#pragma unroll
        for (int ks = 0; ks < 4; ks++) {
            uint32_t ah[4][4], al[4][4], bh[2][4], bl[2][4];
#pragma unroll
            for (int i = 0; i < 4; i++) {
                uint32_t off = SW((a_row + i * 16) * 128 + ks * 32 + a_kb);
                ldsm4(ah[i], base + A_HI + off);
                ldsm4(al[i], base + A_LO + off);
            }
            if constexpr (MODE == 0) {
#pragma unroll
                for (int j2 = 0; j2 < 2; j2++) {
                    uint32_t row = ks * 16 + tb_row_lo;
                    uint32_t chunk = ((uint32_t)(warp_n * 32 + j2 * 16) >> 3) + tb_cadd;
                    uint32_t off = row * 256 + ((chunk ^ (row & 15)) << 4);
                    ldsm4t(bh[j2], base + B_HI + off);
                    ldsm4t(bl[j2], base + B_LO + off);
                }
            } else {
#pragma unroll
                for (int j2 = 0; j2 < 2; j2++) {
                    uint32_t off = SW((b_row + j2 * 16) * 128 + ks * 32 + b_kb);
                    ldsm4(bh[j2], base + B_HI + off);
                    ldsm4(bl[j2], base + B_LO + off);
                }
            }
#pragma unroll
            for (int i = 0; i < 4; i++)
#pragma unroll
                for (int j = 0; j < 4; j++) {
                    int j2 = j >> 1, sub = (j & 1) * 2;
                    mma16816(acc[i][j], ah[i], bh[j2][sub], bh[j2][sub + 1]);
                    mma16816(acc[i][j], ah[i], bl[j2][sub], bl[j2][sub + 1]);
                    mma16816(acc[i][j], al[i], bh[j2][sub], bh[j2][sub + 1]);
                }
        }
        // refill the stage freed two iterations ago (tile kt-1's stage is next-next)
        if (kt + 2 < NK) {
            int ns = stage + 2; if (ns >= NSTAGE) ns -= NSTAGE;
            fill(ns, kt + 2);
            CP_COMMIT();
        }
        stage = (stage + 1 < NSTAGE) ? stage + 1 : 0;
    }

    // ---------------- epilogue ----------------
    const int r4 = lane >> 2, tig = lane & 3;
#pragma unroll
    for (int i = 0; i < 4; i++) {
#pragma unroll
        for (int j = 0; j < 4; j++) {
            int row0 = warp_m * 64 + i * 16 + r4;
            int row1 = row0 + 8;
            int cl = warp_n * 32 + j * 8 + tig * 2;
            float v00 = acc[i][j][0], v01 = acc[i][j][1];
            float v10 = acc[i][j][2], v11 = acc[i][j][3];
            if constexpr (MODE == 0) {
                float s0 = scS[cl], s1 = scS[cl + 1];
                uint32_t h, l;
                size_t o0 = ((size_t)(b * C_ + row0)) * E_ + m0 + cl;
                size_t o1 = ((size_t)(b * C_ + row1)) * E_ + m0 + cl;
                split2(v00 * s0, v01 * s1, h, l);
                *(uint32_t*)(g_Mt_hi + o0) = h; *(uint32_t*)(g_Mt_lo + o0) = l;
                split2(v10 * s0, v11 * s1, h, l);
                *(uint32_t*)(g_Mt_hi + o1) = h; *(uint32_t*)(g_Mt_lo + o1) = l;
            } else if constexpr (MODE == 1) {
                float s0 = scS[row0], s1 = scS[row1];
                uint32_t h, l;
                size_t o0 = ((size_t)(b * N_ + m0 + row0)) * C_ + cl;
                size_t o1 = ((size_t)(b * N_ + m0 + row1)) * C_ + cl;
                split2(v00 * s0, v01 * s0, h, l);
                *(uint32_t*)(g_o2_hi + o0) = h; *(uint32_t*)(g_o2_lo + o0) = l;
                split2(v10 * s1, v11 * s1, h, l);
                *(uint32_t*)(g_o2_hi + o1) = h; *(uint32_t*)(g_o2_lo + o1) = l;
            } else {
                float s0 = scS[cl], s1 = scS[cl + 1];
                float* op0 = outp + (size_t)(m0 + row0) * C_ + cl;
                float* op1 = outp + (size_t)(m0 + row1) * C_ + cl;
                op0[0] = v00 + s0; op0[1] = v01 + s1;
                op1[0] = v10 + s0; op1[1] = v11 + s1;
            }
        }
    }
}

// ---------------- launch (gemm_tc<0> is 4th for ncu) ----------------
extern "C" void kernel_launch(void* const* d_in, const int* in_sizes, int n_in,
                              void* d_out, int out_size) {
    const float* x    = (const float*)d_in[0];
    const float* H    = (const float*)d_in[1];
    const float* W    = (const float*)d_in[2];
    const float* bias = (const float*)d_in[3];
    float* out = (float*)d_out;

    cudaFuncSetAttribute(gemm_tc<0>, cudaFuncAttributeMaxDynamicSharedMemorySize, DSMEM);
    cudaFuncSetAttribute(gemm_tc<1>, cudaFuncAttributeMaxDynamicSharedMemorySize, DSMEM);
    cudaFuncSetAttribute(gemm_tc<2>, cudaFuncAttributeMaxDynamicSharedMemorySize, DSMEM);

    hsplit_dv_kernel<<<B_ * N_, 128>>>(H);                           // 1
    de_part_kernel<<<dim3(E_ / 256, 8, B_), 256>>>(H);               // 2
    xt_kernel<<<dim3(N_ / 32, C_ / 32, B_), dim3(32, 8)>>>(x);       // 3
    gemm_tc<0><<<dim3(E_ / 128, B_), 256, DSMEM>>>(nullptr, nullptr);     // 4 <- profiled
    wsplit_kernel<<<(C_ * C_) / 256, 256>>>(W);                      // 5
    gemm_tc<1><<<dim3(N_ / 128, B_), 256, DSMEM>>>(nullptr, nullptr);     // 6
    gemm_tc<2><<<(B_ * N_) / 128, 256, DSMEM>>>(bias, out);          // 7
}

// round 14
// speedup vs baseline: 1.0083x; 1.0083x over previous
#include <cuda_runtime.h>
#include <cuda_bf16.h>
#include <cstdint>

#define B_   8
#define N_   4096
#define E_   2048
#define C_   128
#define EPS_ 1e-6f

#define KT   64
#define STAGE_BYTES 65536
#define A_HI 0
#define A_LO 16384
#define B_HI 32768
#define B_LO 49152
#define TILE0 1024
#define DSMEM (1024 + 1024 + 2 * STAGE_BYTES)

#define SW(o) ((o) ^ ((((uint32_t)(o)) >> 3) & 0x70u))

// ---------------- static device scratch ----------------
__device__ float g_dv[B_ * N_];
__device__ float g_de_part[B_ * 8 * E_];
__device__ __nv_bfloat16 g_H_hi[(size_t)B_ * N_ * E_];
__device__ __nv_bfloat16 g_H_lo[(size_t)B_ * N_ * E_];
__device__ __nv_bfloat16 g_xt_hi[(size_t)B_ * C_ * N_];
__device__ __nv_bfloat16 g_xt_lo[(size_t)B_ * C_ * N_];
__device__ __nv_bfloat16 g_W_hi[C_ * C_];
__device__ __nv_bfloat16 g_W_lo[C_ * C_];
__device__ __nv_bfloat16 g_Mt_hi[(size_t)B_ * C_ * E_];
__device__ __nv_bfloat16 g_Mt_lo[(size_t)B_ * C_ * E_];
__device__ __nv_bfloat16 g_o2_hi[(size_t)B_ * N_ * C_];
__device__ __nv_bfloat16 g_o2_lo[(size_t)B_ * N_ * C_];

// ---------------- helpers ----------------
__device__ __forceinline__ uint32_t s2u(const void* p) {
    uint32_t a;
    asm("{ .reg .u64 t; cvta.to.shared.u64 t, %1; cvt.u32.u64 %0, t; }" : "=r"(a) : "l"(p));
    return a;
}
__device__ __forceinline__ void cpa16(uint32_t dst, const void* src) {
    asm volatile("cp.async.cg.shared.global [%0], [%1], 16;" :: "r"(dst), "l"(src));
}
#define CP_COMMIT() asm volatile("cp.async.commit_group;" ::: "memory")
#define CP_WAIT0()  asm volatile("cp.async.wait_group 0;" ::: "memory")

__device__ __forceinline__ void ldsm4(uint32_t r[4], uint32_t addr) {
    asm volatile("ldmatrix.sync.aligned.m8n8.x4.shared.b16 {%0,%1,%2,%3}, [%4];"
        : "=r"(r[0]), "=r"(r[1]), "=r"(r[2]), "=r"(r[3]) : "r"(addr));
}
__device__ __forceinline__ void ldsm4t(uint32_t r[4], uint32_t addr) {
    asm volatile("ldmatrix.sync.aligned.m8n8.x4.trans.shared.b16 {%0,%1,%2,%3}, [%4];"
        : "=r"(r[0]), "=r"(r[1]), "=r"(r[2]), "=r"(r[3]) : "r"(addr));
}
__device__ __forceinline__ void mma16816(float c[4], const uint32_t a[4], uint32_t b0, uint32_t b1) {
    asm volatile("mma.sync.aligned.m16n8k16.row.col.f32.bf16.bf16.f32 "
        "{%0,%1,%2,%3}, {%4,%5,%6,%7}, {%8,%9}, {%0,%1,%2,%3};"
        : "+f"(c[0]), "+f"(c[1]), "+f"(c[2]), "+f"(c[3])
        : "r"(a[0]), "r"(a[1]), "r"(a[2]), "r"(a[3]), "r"(b0), "r"(b1));
}
__device__ __forceinline__ void split2(float f0, float f1, uint32_t& h, uint32_t& l) {
    unsigned short h0 = __bfloat16_as_ushort(__float2bfloat16(f0));
    unsigned short h1 = __bfloat16_as_ushort(__float2bfloat16(f1));
    float r0 = f0 - __bfloat162float(__ushort_as_bfloat16(h0));
    float r1 = f1 - __bfloat162float(__ushort_as_bfloat16(h1));
    unsigned short l0 = __bfloat16_as_ushort(__float2bfloat16(r0));
    unsigned short l1 = __bfloat16_as_ushort(__float2bfloat16(r1));
    h = (uint32_t)h0 | ((uint32_t)h1 << 16);
    l = (uint32_t)l0 | ((uint32_t)l1 << 16);
}

// ---------------- H split + Dv in ONE streaming pass over H ----------------
__global__ void hsplit_dv_kernel(const float* __restrict__ H) {
    int row = blockIdx.x;  // b*N + n
    int t = threadIdx.x;
    const float4* p = (const float4*)(H + (size_t)row * E_);
    __nv_bfloat16* hh = g_H_hi + (size_t)row * E_;
    __nv_bfloat16* hl = g_H_lo + (size_t)row * E_;
    float s = 0.f;
#pragma unroll
    for (int i = 0; i < 4; i++) {
        int e4 = t + i * 128;
        float4 v = p[e4];
        s += (v.x + v.y) + (v.z + v.w);
        uint32_t h01, l01, h23, l23;
        split2(v.x, v.y, h01, l01);
        split2(v.z, v.w, h23, l23);
        *(uint2*)(hh + e4 * 4) = make_uint2(h01, h23);
        *(uint2*)(hl + e4 * 4) = make_uint2(l01, l23);
    }
    __shared__ float red[4];
#pragma unroll
    for (int o = 16; o > 0; o >>= 1) s += __shfl_down_sync(0xffffffffu, s, o);
    if ((t & 31) == 0) red[t >> 5] = s;
    __syncthreads();
    if (t == 0) g_dv[row] = rsqrtf(red[0] + red[1] + red[2] + red[3] + EPS_);
}

// ---------------- De partial sums ----------------
__global__ void de_part_kernel(const float* __restrict__ H) {
    int e = blockIdx.x * 256 + threadIdx.x;
    int chunk = blockIdx.y, b = blockIdx.z;
    const float* p = H + ((size_t)b * N_ + (size_t)chunk * 512) * E_ + e;
    float s0 = 0.f, s1 = 0.f, s2 = 0.f, s3 = 0.f;
#pragma unroll 4
    for (int n = 0; n < 512; n += 4) {
        s0 += p[(size_t)(n + 0) * E_];
        s1 += p[(size_t)(n + 1) * E_];
        s2 += p[(size_t)(n + 2) * E_];
        s3 += p[(size_t)(n + 3) * E_];
    }
    g_de_part[((b * 8) + chunk) * E_ + e] = (s0 + s1) + (s2 + s3);
}

// xt[b][c][n] = split( x[b][n][c] * dv[b][n] )
__global__ void xt_kernel(const float* __restrict__ x) {
    __shared__ float t[32][33];
    int b = blockIdx.z, n0 = blockIdx.x * 32, c0 = blockIdx.y * 32;
    int tx = threadIdx.x, ty = threadIdx.y;
#pragma unroll
    for (int i = 0; i < 4; i++) {
        int n = n0 + ty + i * 8;
        t[ty + i * 8][tx] = x[((size_t)(b * N_ + n)) * C_ + c0 + tx] * g_dv[b * N_ + n];
    }
    __syncthreads();
#pragma unroll
    for (int i = 0; i < 4; i++) {
        int c = c0 + ty + i * 8;
        float f = t[tx][ty + i * 8];
        __nv_bfloat16 h = __float2bfloat16(f);
        __nv_bfloat16 l = __float2bfloat16(f - __bfloat162float(h));
        size_t o = ((size_t)(b * C_ + c)) * N_ + n0 + tx;
        g_xt_hi[o] = h;
        g_xt_lo[o] = l;
    }
}

__global__ void wsplit_kernel(const float* __restrict__ W) {
    int i = blockIdx.x * 256 + threadIdx.x;
    float f = W[i];
    __nv_bfloat16 h = __float2bfloat16(f);
    g_W_hi[i] = h;
    g_W_lo[i] = __float2bfloat16(f - __bfloat162float(h));
}

// ---------------- templated HMMA GEMM, 2-stage cp.async, term-ordered MMAs ----------------
// MODE 0: Mt[c, e]  = (xt . H) * De^-1[e]   A=xt K-major, B=H natural + ldsm.trans  grid(16,8)
// MODE 1: o2[n, c]  = (H . Mt) * dv[n]      A=H K-major,  B=Mt K-major              grid(32,8)
// MODE 2: out[r, c] = (o2 . W) + bias[c]                                            grid(256)
template<int MODE>
__global__ __launch_bounds__(256) void gemm_tc(const float* __restrict__ bias,
                                               float* __restrict__ outp) {
    constexpr int NK = (MODE == 0) ? N_ / KT : ((MODE == 1) ? E_ / KT : C_ / KT);
    extern __shared__ char smem[];
    uint32_t raw = s2u(smem);
    uint32_t sb = (raw + 1023u) & ~1023u;
    float* scS = (float*)(smem + (sb - raw));
    const int tid = threadIdx.x;
    const int lane = tid & 31, wid = tid >> 5;
    const int warp_m = wid >> 2, warp_n = wid & 3;
    const int m0 = blockIdx.x * 128;
    const int b = (MODE == 2) ? 0 : blockIdx.y;

    if (tid < 128) {
        if (MODE == 0) {
            float s = 0.f;
#pragma unroll
            for (int c = 0; c < 8; c++) s += g_de_part[(b * 8 + c) * E_ + m0 + tid];
            scS[tid] = 1.0f / (s + EPS_);
        }
        if (MODE == 1) scS[tid] = g_dv[b * N_ + m0 + tid];
        if (MODE == 2) scS[tid] = bias[tid];
    }

    const __nv_bfloat16* xh = g_xt_hi + (size_t)b * C_ * N_;
    const __nv_bfloat16* xl = g_xt_lo + (size_t)b * C_ * N_;
    const __nv_bfloat16* Hh = g_H_hi + (size_t)b * N_ * E_;
    const __nv_bfloat16* Hl = g_H_lo + (size_t)b * N_ * E_;
    const __nv_bfloat16* mh = g_Mt_hi + (size_t)b * C_ * E_;
    const __nv_bfloat16* ml = g_Mt_lo + (size_t)b * C_ * E_;

    auto fill = [&](int s, int kt) {
        uint32_t base = sb + TILE0 + s * STAGE_BYTES;
        int koff = kt * KT;
        if constexpr (MODE == 0) {
#pragma unroll
            for (int i = 0; i < 4; i++) {
                int idx = tid + i * 256, row = idx >> 3, q = idx & 7;
                uint32_t off = SW(row * 128 + q * 16);
                cpa16(base + A_HI + off, xh + (size_t)row * N_ + koff + q * 8);
                cpa16(base + A_LO + off, xl + (size_t)row * N_ + koff + q * 8);
            }
#pragma unroll
            for (int i = 0; i < 4; i++) {
                int idx = tid + i * 256, row = idx >> 4, c = idx & 15;
                uint32_t off = row * 256 + ((uint32_t)(c ^ (row & 15)) << 4);
                cpa16(base + B_HI + off, Hh + (size_t)(koff + row) * E_ + m0 + c * 8);
                cpa16(base + B_LO + off, Hl + (size_t)(koff + row) * E_ + m0 + c * 8);
            }
        } else if constexpr (MODE == 1) {
#pragma unroll
            for (int i = 0; i < 4; i++) {
                int idx = tid + i * 256, row = idx >> 3, q = idx & 7;
                uint32_t off = SW(row * 128 + q * 16);
                cpa16(base + A_HI + off, Hh + (size_t)(m0 + row) * E_ + koff + q * 8);
                cpa16(base + A_LO + off, Hl + (size_t)(m0 + row) * E_ + koff + q * 8);
                cpa16(base + B_HI + off, mh + (size_t)row * E_ + koff + q * 8);
                cpa16(base + B_LO + off, ml + (size_t)row * E_ + koff + q * 8);
            }
        } else {
#pragma unroll
            for (int i = 0; i < 4; i++) {
                int idx = tid + i * 256, row = idx >> 3, q = idx & 7;
                uint32_t off = SW(row * 128 + q * 16);
                cpa16(base + A_HI + off, g_o2_hi + (size_t)(m0 + row) * C_ + koff + q * 8);
                cpa16(base + A_LO + off, g_o2_lo + (size_t)(m0 + row) * C_ + koff + q * 8);
                cpa16(base + B_HI + off, g_W_hi + (size_t)row * C_ + koff + q * 8);
                cpa16(base + B_LO + off, g_W_lo + (size_t)row * C_ + koff + q * 8);
            }
        }
    };

    float acc[4][4][4];
#pragma unroll
    for (int i = 0; i < 4; i++)
#pragma unroll
        for (int j = 0; j < 4; j++)
#pragma unroll
            for (int k = 0; k < 4; k++) acc[i][j][k] = 0.f;

    const int a_row = warp_m * 64 + (lane & 15);
    const int a_kb  = (lane >> 4) * 16;
    const int b_row = warp_n * 32 + (lane & 7) + ((lane >> 4) << 3);
    const int b_kb  = ((lane >> 3) & 1) * 16;
    const uint32_t tb_row_lo = ((lane >> 3) & 1) * 8 + (lane & 7);
    const uint32_t tb_cadd   = lane >> 4;

    fill(0, 0);
    CP_COMMIT();

    for (int kt = 0; kt < NK; kt++) {
        int cur = kt & 1;
        CP_WAIT0();
        __syncthreads();
        if (kt + 1 < NK) { fill(cur ^ 1, kt + 1); CP_COMMIT(); }

        uint32_t base = sb + TILE0 + cur * STAGE_BYTES;
#pragma unroll
        for (int ks = 0; ks < 4; ks++) {
            uint32_t ah[4][4], al[4][4], bh[2][4], bl[2][4];
#pragma unroll
            for (int i = 0; i < 4; i++) {
                uint32_t off = SW((a_row + i * 16) * 128 + ks * 32 + a_kb);
                ldsm4(ah[i], base + A_HI + off);
                ldsm4(al[i], base + A_LO + off);
            }
            if constexpr (MODE == 0) {
#pragma unroll
                for (int j2 = 0; j2 < 2; j2++) {
                    uint32_t row = ks * 16 + tb_row_lo;
                    uint32_t chunk = ((uint32_t)(warp_n * 32 + j2 * 16) >> 3) + tb_cadd;
                    uint32_t off = row * 256 + ((chunk ^ (row & 15)) << 4);
                    ldsm4t(bh[j2], base + B_HI + off);
                    ldsm4t(bl[j2], base + B_LO + off);
                }
            } else {
#pragma unroll
                for (int j2 = 0; j2 < 2; j2++) {
                    uint32_t off = SW((b_row + j2 * 16) * 128 + ks * 32 + b_kb);
                    ldsm4(bh[j2], base + B_HI + off);
                    ldsm4(bl[j2], base + B_LO + off);
                }
            }
            // Term-ordered MMA issue: all 16 accs per term -> same-acc MMAs are
            // 16 independent instructions apart (no exposed HMMA RAW latency).
#pragma unroll
            for (int i = 0; i < 4; i++)
#pragma unroll
                for (int j = 0; j < 4; j++) {
                    int j2 = j >> 1, sub = (j & 1) * 2;
                    mma16816(acc[i][j], ah[i], bh[j2][sub], bh[j2][sub + 1]);
                }
#pragma unroll
            for (int i = 0; i < 4; i++)
#pragma unroll
                for (int j = 0; j < 4; j++) {
                    int j2 = j >> 1, sub = (j & 1) * 2;
                    mma16816(acc[i][j], ah[i], bl[j2][sub], bl[j2][sub + 1]);
                }
#pragma unroll
            for (int i = 0; i < 4; i++)
#pragma unroll
                for (int j = 0; j < 4; j++) {
                    int j2 = j >> 1, sub = (j & 1) * 2;
                    mma16816(acc[i][j], al[i], bh[j2][sub], bh[j2][sub + 1]);
                }
        }
    }

    // ---------------- epilogue ----------------
    const int r4 = lane >> 2, tig = lane & 3;
#pragma unroll
    for (int i = 0; i < 4; i++) {
#pragma unroll
        for (int j = 0; j < 4; j++) {
            int row0 = warp_m * 64 + i * 16 + r4;
            int row1 = row0 + 8;
            int cl = warp_n * 32 + j * 8 + tig * 2;
            float v00 = acc[i][j][0], v01 = acc[i][j][1];
            float v10 = acc[i][j][2], v11 = acc[i][j][3];
            if constexpr (MODE == 0) {
                float s0 = scS[cl], s1 = scS[cl + 1];
                uint32_t h, l;
                size_t o0 = ((size_t)(b * C_ + row0)) * E_ + m0 + cl;
                size_t o1 = ((size_t)(b * C_ + row1)) * E_ + m0 + cl;
                split2(v00 * s0, v01 * s1, h, l);
                *(uint32_t*)(g_Mt_hi + o0) = h; *(uint32_t*)(g_Mt_lo + o0) = l;
                split2(v10 * s0, v11 * s1, h, l);
                *(uint32_t*)(g_Mt_hi + o1) = h; *(uint32_t*)(g_Mt_lo + o1) = l;
            } else if constexpr (MODE == 1) {
                float s0 = scS[row0], s1 = scS[row1];
                uint32_t h, l;
                size_t o0 = ((size_t)(b * N_ + m0 + row0)) * C_ + cl;
                size_t o1 = ((size_t)(b * N_ + m0 + row1)) * C_ + cl;
                split2(v00 * s0, v01 * s0, h, l);
                *(uint32_t*)(g_o2_hi + o0) = h; *(uint32_t*)(g_o2_lo + o0) = l;
                split2(v10 * s1, v11 * s1, h, l);
                *(uint32_t*)(g_o2_hi + o1) = h; *(uint32_t*)(g_o2_lo + o1) = l;
            } else {
                float s0 = scS[cl], s1 = scS[cl + 1];
                float* op0 = outp + (size_t)(m0 + row0) * C_ + cl;
                float* op1 = outp + (size_t)(m0 + row1) * C_ + cl;
                op0[0] = v00 + s0; op0[1] = v01 + s1;
                op1[0] = v10 + s0; op1[1] = v11 + s1;
            }
        }
    }
}

// ---------------- launch (gemm_tc<0> is 4th for ncu) ----------------
extern "C" void kernel_launch(void* const* d_in, const int* in_sizes, int n_in,
                              void* d_out, int out_size) {
    const float* x    = (const float*)d_in[0];
    const float* H    = (const float*)d_in[1];
    const float* W    = (const float*)d_in[2];
    const float* bias = (const float*)d_in[3];
    float* out = (float*)d_out;

    cudaFuncSetAttribute(gemm_tc<0>, cudaFuncAttributeMaxDynamicSharedMemorySize, DSMEM);
    cudaFuncSetAttribute(gemm_tc<1>, cudaFuncAttributeMaxDynamicSharedMemorySize, DSMEM);
    cudaFuncSetAttribute(gemm_tc<2>, cudaFuncAttributeMaxDynamicSharedMemorySize, DSMEM);

    hsplit_dv_kernel<<<B_ * N_, 128>>>(H);                           // 1
    de_part_kernel<<<dim3(E_ / 256, 8, B_), 256>>>(H);               // 2
    xt_kernel<<<dim3(N_ / 32, C_ / 32, B_), dim3(32, 8)>>>(x);       // 3
    gemm_tc<0><<<dim3(E_ / 128, B_), 256, DSMEM>>>(nullptr, nullptr);     // 4 <- profiled
    wsplit_kernel<<<(C_ * C_) / 256, 256>>>(W);                      // 5
    gemm_tc<1><<<dim3(N_ / 128, B_), 256, DSMEM>>>(nullptr, nullptr);     // 6
    gemm_tc<2><<<(B_ * N_) / 128, 256, DSMEM>>>(bias, out);          // 7
}

// round 15
// speedup vs baseline: 1.0331x; 1.0246x over previous
#include <cuda_runtime.h>
#include <cuda_bf16.h>
#include <cstdint>

#define B_   8
#define N_   4096
#define E_   2048
#define C_   128
#define EPS_ 1e-6f

#define KT   64
#define STAGE_BYTES 65536
#define A_HI 0
#define A_LO 16384
#define B_HI 32768
#define B_LO 49152
#define TILE0 1024
#define DSMEM (1024 + 1024 + 2 * STAGE_BYTES)

#define SW(o) ((o) ^ ((((uint32_t)(o)) >> 3) & 0x70u))

// ---------------- static device scratch ----------------
__device__ float g_dv[B_ * N_];
__device__ float g_de_part[B_ * 8 * E_];
__device__ __nv_bfloat16 g_H_hi[(size_t)B_ * N_ * E_];
__device__ __nv_bfloat16 g_H_lo[(size_t)B_ * N_ * E_];
__device__ __nv_bfloat16 g_xt_hi[(size_t)B_ * C_ * N_];
__device__ __nv_bfloat16 g_xt_lo[(size_t)B_ * C_ * N_];
__device__ __nv_bfloat16 g_W_hi[C_ * C_];
__device__ __nv_bfloat16 g_W_lo[C_ * C_];
__device__ __nv_bfloat16 g_Mt_hi[(size_t)B_ * C_ * E_];
__device__ __nv_bfloat16 g_Mt_lo[(size_t)B_ * C_ * E_];
__device__ __nv_bfloat16 g_o2_hi[(size_t)B_ * N_ * C_];
__device__ __nv_bfloat16 g_o2_lo[(size_t)B_ * N_ * C_];

// ---------------- helpers ----------------
__device__ __forceinline__ uint32_t s2u(const void* p) {
    uint32_t a;
    asm("{ .reg .u64 t; cvta.to.shared.u64 t, %1; cvt.u32.u64 %0, t; }" : "=r"(a) : "l"(p));
    return a;
}
__device__ __forceinline__ void cpa16(uint32_t dst, const void* src) {
    asm volatile("cp.async.cg.shared.global [%0], [%1], 16;" :: "r"(dst), "l"(src));
}
#define CP_COMMIT() asm volatile("cp.async.commit_group;" ::: "memory")
#define CP_WAIT0()  asm volatile("cp.async.wait_group 0;" ::: "memory")

__device__ __forceinline__ void ldsm4(uint32_t r[4], uint32_t addr) {
    asm volatile("ldmatrix.sync.aligned.m8n8.x4.shared.b16 {%0,%1,%2,%3}, [%4];"
        : "=r"(r[0]), "=r"(r[1]), "=r"(r[2]), "=r"(r[3]) : "r"(addr));
}
__device__ __forceinline__ void ldsm4t(uint32_t r[4], uint32_t addr) {
    asm volatile("ldmatrix.sync.aligned.m8n8.x4.trans.shared.b16 {%0,%1,%2,%3}, [%4];"
        : "=r"(r[0]), "=r"(r[1]), "=r"(r[2]), "=r"(r[3]) : "r"(addr));
}
__device__ __forceinline__ void mma16816(float c[4], const uint32_t a[4], uint32_t b0, uint32_t b1) {
    asm volatile("mma.sync.aligned.m16n8k16.row.col.f32.bf16.bf16.f32 "
        "{%0,%1,%2,%3}, {%4,%5,%6,%7}, {%8,%9}, {%0,%1,%2,%3};"
        : "+f"(c[0]), "+f"(c[1]), "+f"(c[2]), "+f"(c[3])
        : "r"(a[0]), "r"(a[1]), "r"(a[2]), "r"(a[3]), "r"(b0), "r"(b1));
}
__device__ __forceinline__ void split2(float f0, float f1, uint32_t& h, uint32_t& l) {
    unsigned short h0 = __bfloat16_as_ushort(__float2bfloat16(f0));
    unsigned short h1 = __bfloat16_as_ushort(__float2bfloat16(f1));
    float r0 = f0 - __bfloat162float(__ushort_as_bfloat16(h0));
    float r1 = f1 - __bfloat162float(__ushort_as_bfloat16(h1));
    unsigned short l0 = __bfloat16_as_ushort(__float2bfloat16(r0));
    unsigned short l1 = __bfloat16_as_ushort(__float2bfloat16(r1));
    h = (uint32_t)h0 | ((uint32_t)h1 << 16);
    l = (uint32_t)l0 | ((uint32_t)l1 << 16);
}

// ---------------- H split + Dv in ONE streaming pass over H ----------------
__global__ void hsplit_dv_kernel(const float* __restrict__ H) {
    int row = blockIdx.x;  // b*N + n
    int t = threadIdx.x;
    const float4* p = (const float4*)(H + (size_t)row * E_);
    __nv_bfloat16* hh = g_H_hi + (size_t)row * E_;
    __nv_bfloat16* hl = g_H_lo + (size_t)row * E_;
    float s = 0.f;
#pragma unroll
    for (int i = 0; i < 4; i++) {
        int e4 = t + i * 128;
        float4 v = p[e4];
        s += (v.x + v.y) + (v.z + v.w);
        uint32_t h01, l01, h23, l23;
        split2(v.x, v.y, h01, l01);
        split2(v.z, v.w, h23, l23);
        *(uint2*)(hh + e4 * 4) = make_uint2(h01, h23);
        *(uint2*)(hl + e4 * 4) = make_uint2(l01, l23);
    }
    __shared__ float red[4];
#pragma unroll
    for (int o = 16; o > 0; o >>= 1) s += __shfl_down_sync(0xffffffffu, s, o);
    if ((t & 31) == 0) red[t >> 5] = s;
    __syncthreads();
    if (t == 0) g_dv[row] = rsqrtf(red[0] + red[1] + red[2] + red[3] + EPS_);
}

// ---------------- De partial sums: read bf16 hi (half the traffic) ----------------
__global__ void de_part_kernel() {
    int e = blockIdx.x * 256 + threadIdx.x;
    int chunk = blockIdx.y, b = blockIdx.z;
    const __nv_bfloat16* p = g_H_hi + ((size_t)b * N_ + (size_t)chunk * 512) * E_ + e;
    float s0 = 0.f, s1 = 0.f, s2 = 0.f, s3 = 0.f;
#pragma unroll 4
    for (int n = 0; n < 512; n += 4) {
        s0 += __bfloat162float(p[(size_t)(n + 0) * E_]);
        s1 += __bfloat162float(p[(size_t)(n + 1) * E_]);
        s2 += __bfloat162float(p[(size_t)(n + 2) * E_]);
        s3 += __bfloat162float(p[(size_t)(n + 3) * E_]);
    }
    g_de_part[((b * 8) + chunk) * E_ + e] = (s0 + s1) + (s2 + s3);
}

// xt[b][c][n] = split( x[b][n][c] * dv[b][n] )
__global__ void xt_kernel(const float* __restrict__ x) {
    __shared__ float t[32][33];
    int b = blockIdx.z, n0 = blockIdx.x * 32, c0 = blockIdx.y * 32;
    int tx = threadIdx.x, ty = threadIdx.y;
#pragma unroll
    for (int i = 0; i < 4; i++) {
        int n = n0 + ty + i * 8;
        t[ty + i * 8][tx] = x[((size_t)(b * N_ + n)) * C_ + c0 + tx] * g_dv[b * N_ + n];
    }
    __syncthreads();
#pragma unroll
    for (int i = 0; i < 4; i++) {
        int c = c0 + ty + i * 8;
        float f = t[tx][ty + i * 8];
        __nv_bfloat16 h = __float2bfloat16(f);
        __nv_bfloat16 l = __float2bfloat16(f - __bfloat162float(h));
        size_t o = ((size_t)(b * C_ + c)) * N_ + n0 + tx;
        g_xt_hi[o] = h;
        g_xt_lo[o] = l;
    }
}

__global__ void wsplit_kernel(const float* __restrict__ W) {
    int i = blockIdx.x * 256 + threadIdx.x;
    float f = W[i];
    __nv_bfloat16 h = __float2bfloat16(f);
    g_W_hi[i] = h;
    g_W_lo[i] = __float2bfloat16(f - __bfloat162float(h));
}

// ---------------- HMMA GEMM: 512 threads, 4x4 warp grid (warp tile 32x32) ----------------
// MODE 0: Mt[c, e]  = (xt . H) * De^-1[e]   A=xt K-major, B=H natural + ldsm.trans  grid(16,8)
// MODE 1: o2[n, c]  = (H . Mt) * dv[n]      A=H K-major,  B=Mt K-major              grid(32,8)
// MODE 2: out[r, c] = (o2 . W) + bias[c]                                            grid(256)
template<int MODE>
__global__ __launch_bounds__(512) void gemm_tc(const float* __restrict__ bias,
                                               float* __restrict__ outp) {
    constexpr int NK = (MODE == 0) ? N_ / KT : ((MODE == 1) ? E_ / KT : C_ / KT);
    extern __shared__ char smem[];
    uint32_t raw = s2u(smem);
    uint32_t sb = (raw + 1023u) & ~1023u;
    float* scS = (float*)(smem + (sb - raw));
    const int tid = threadIdx.x;
    const int lane = tid & 31, wid = tid >> 5;
    const int warp_m = wid >> 2, warp_n = wid & 3;   // 4 x 4 warps
    const int m0 = blockIdx.x * 128;
    const int b = (MODE == 2) ? 0 : blockIdx.y;

    if (tid < 128) {
        if (MODE == 0) {
            float s = 0.f;
#pragma unroll
            for (int c = 0; c < 8; c++) s += g_de_part[(b * 8 + c) * E_ + m0 + tid];
            scS[tid] = 1.0f / (s + EPS_);
        }
        if (MODE == 1) scS[tid] = g_dv[b * N_ + m0 + tid];
        if (MODE == 2) scS[tid] = bias[tid];
    }

    const __nv_bfloat16* xh = g_xt_hi + (size_t)b * C_ * N_;
    const __nv_bfloat16* xl = g_xt_lo + (size_t)b * C_ * N_;
    const __nv_bfloat16* Hh = g_H_hi + (size_t)b * N_ * E_;
    const __nv_bfloat16* Hl = g_H_lo + (size_t)b * N_ * E_;
    const __nv_bfloat16* mh = g_Mt_hi + (size_t)b * C_ * E_;
    const __nv_bfloat16* ml = g_Mt_lo + (size_t)b * C_ * E_;

    auto fill = [&](int s, int kt) {
        uint32_t base = sb + TILE0 + s * STAGE_BYTES;
        int koff = kt * KT;
        if constexpr (MODE == 0) {
#pragma unroll
            for (int i = 0; i < 2; i++) {
                int idx = tid + i * 512, row = idx >> 3, q = idx & 7;
                uint32_t off = SW(row * 128 + q * 16);
                cpa16(base + A_HI + off, xh + (size_t)row * N_ + koff + q * 8);
                cpa16(base + A_LO + off, xl + (size_t)row * N_ + koff + q * 8);
            }
#pragma unroll
            for (int i = 0; i < 2; i++) {
                int idx = tid + i * 512, row = idx >> 4, c = idx & 15;
                uint32_t off = row * 256 + ((uint32_t)(c ^ (row & 15)) << 4);
                cpa16(base + B_HI + off, Hh + (size_t)(koff + row) * E_ + m0 + c * 8);
                cpa16(base + B_LO + off, Hl + (size_t)(koff + row) * E_ + m0 + c * 8);
            }
        } else if constexpr (MODE == 1) {
#pragma unroll
            for (int i = 0; i < 2; i++) {
                int idx = tid + i * 512, row = idx >> 3, q = idx & 7;
                uint32_t off = SW(row * 128 + q * 16);
                cpa16(base + A_HI + off, Hh + (size_t)(m0 + row) * E_ + koff + q * 8);
                cpa16(base + A_LO + off, Hl + (size_t)(m0 + row) * E_ + koff + q * 8);
                cpa16(base + B_HI + off, mh + (size_t)row * E_ + koff + q * 8);
                cpa16(base + B_LO + off, ml + (size_t)row * E_ + koff + q * 8);
            }
        } else {
#pragma unroll
            for (int i = 0; i < 2; i++) {
                int idx = tid + i * 512, row = idx >> 3, q = idx & 7;
                uint32_t off = SW(row * 128 + q * 16);
                cpa16(base + A_HI + off, g_o2_hi + (size_t)(m0 + row) * C_ + koff + q * 8);
                cpa16(base + A_LO + off, g_o2_lo + (size_t)(m0 + row) * C_ + koff + q * 8);
                cpa16(base + B_HI + off, g_W_hi + (size_t)row * C_ + koff + q * 8);
                cpa16(base + B_LO + off, g_W_lo + (size_t)row * C_ + koff + q * 8);
            }
        }
    };

    float acc[2][4][4];
#pragma unroll
    for (int i = 0; i < 2; i++)
#pragma unroll
        for (int j = 0; j < 4; j++)
#pragma unroll
            for (int k = 0; k < 4; k++) acc[i][j][k] = 0.f;

    const int a_row = warp_m * 32 + (lane & 15);
    const int a_kb  = (lane >> 4) * 16;
    const int b_row = warp_n * 32 + (lane & 7) + ((lane >> 4) << 3);
    const int b_kb  = ((lane >> 3) & 1) * 16;
    const uint32_t tb_row_lo = ((lane >> 3) & 1) * 8 + (lane & 7);
    const uint32_t tb_cadd   = lane >> 4;

    fill(0, 0);
    CP_COMMIT();

    for (int kt = 0; kt < NK; kt++) {
        int cur = kt & 1;
        CP_WAIT0();
        __syncthreads();
        if (kt + 1 < NK) { fill(cur ^ 1, kt + 1); CP_COMMIT(); }

        uint32_t base = sb + TILE0 + cur * STAGE_BYTES;
#pragma unroll
        for (int ks = 0; ks < 4; ks++) {
            uint32_t ah[2][4], al[2][4], bh[2][4], bl[2][4];
#pragma unroll
            for (int i = 0; i < 2; i++) {
                uint32_t off = SW((a_row + i * 16) * 128 + ks * 32 + a_kb);
                ldsm4(ah[i], base + A_HI + off);
                ldsm4(al[i], base + A_LO + off);
            }
            if constexpr (MODE == 0) {
#pragma unroll
                for (int j2 = 0; j2 < 2; j2++) {
                    uint32_t row = ks * 16 + tb_row_lo;
                    uint32_t chunk = ((uint32_t)(warp_n * 32 + j2 * 16) >> 3) + tb_cadd;
                    uint32_t off = row * 256 + ((chunk ^ (row & 15)) << 4);
                    ldsm4t(bh[j2], base + B_HI + off);
                    ldsm4t(bl[j2], base + B_LO + off);
                }
            } else {
#pragma unroll
                for (int j2 = 0; j2 < 2; j2++) {
                    uint32_t off = SW((b_row + j2 * 16) * 128 + ks * 32 + b_kb);
                    ldsm4(bh[j2], base + B_HI + off);
                    ldsm4(bl[j2], base + B_LO + off);
                }
            }
#pragma unroll
            for (int i = 0; i < 2; i++)
#pragma unroll
                for (int j = 0; j < 4; j++) {
                    int j2 = j >> 1, sub = (j & 1) * 2;
                    mma16816(acc[i][j], ah[i], bh[j2][sub], bh[j2][sub + 1]);
                    mma16816(acc[i][j], ah[i], bl[j2][sub], bl[j2][sub + 1]);
                    mma16816(acc[i][j], al[i], bh[j2][sub], bh[j2][sub + 1]);
                }
        }
    }

    // ---------------- epilogue ----------------
    const int r4 = lane >> 2, tig = lane & 3;
#pragma unroll
    for (int i = 0; i < 2; i++) {
#pragma unroll
        for (int j = 0; j < 4; j++) {
            int row0 = warp_m * 32 + i * 16 + r4;
            int row1 = row0 + 8;
            int cl = warp_n * 32 + j * 8 + tig * 2;
            float v00 = acc[i][j][0], v01 = acc[i][j][1];
            float v10 = acc[i][j][2], v11 = acc[i][j][3];
            if constexpr (MODE == 0) {
                float s0 = scS[cl], s1 = scS[cl + 1];
                uint32_t h, l;
                size_t o0 = ((size_t)(b * C_ + row0)) * E_ + m0 + cl;
                size_t o1 = ((size_t)(b * C_ + row1)) * E_ + m0 + cl;
                split2(v00 * s0, v01 * s1, h, l);
                *(uint32_t*)(g_Mt_hi + o0) = h; *(uint32_t*)(g_Mt_lo + o0) = l;
                split2(v10 * s0, v11 * s1, h, l);
                *(uint32_t*)(g_Mt_hi + o1) = h; *(uint32_t*)(g_Mt_lo + o1) = l;
            } else if constexpr (MODE == 1) {
                float s0 = scS[row0], s1 = scS[row1];
                uint32_t h, l;
                size_t o0 = ((size_t)(b * N_ + m0 + row0)) * C_ + cl;
                size_t o1 = ((size_t)(b * N_ + m0 + row1)) * C_ + cl;
                split2(v00 * s0, v01 * s0, h, l);
                *(uint32_t*)(g_o2_hi + o0) = h; *(uint32_t*)(g_o2_lo + o0) = l;
                split2(v10 * s1, v11 * s1, h, l);
                *(uint32_t*)(g_o2_hi + o1) = h; *(uint32_t*)(g_o2_lo + o1) = l;
            } else {
                float s0 = scS[cl], s1 = scS[cl + 1];
                float* op0 = outp + (size_t)(m0 + row0) * C_ + cl;
                float* op1 = outp + (size_t)(m0 + row1) * C_ + cl;
                op0[0] = v00 + s0; op0[1] = v01 + s1;
                op1[0] = v10 + s0; op1[1] = v11 + s1;
            }
        }
    }
}

// ---------------- launch (gemm_tc<0> is 4th for ncu) ----------------
extern "C" void kernel_launch(void* const* d_in, const int* in_sizes, int n_in,
                              void* d_out, int out_size) {
    const float* x    = (const float*)d_in[0];
    const float* H    = (const float*)d_in[1];
    const float* W    = (const float*)d_in[2];
    const float* bias = (const float*)d_in[3];
    float* out = (float*)d_out;

    cudaFuncSetAttribute(gemm_tc<0>, cudaFuncAttributeMaxDynamicSharedMemorySize, DSMEM);
    cudaFuncSetAttribute(gemm_tc<1>, cudaFuncAttributeMaxDynamicSharedMemorySize, DSMEM);
    cudaFuncSetAttribute(gemm_tc<2>, cudaFuncAttributeMaxDynamicSharedMemorySize, DSMEM);

    hsplit_dv_kernel<<<B_ * N_, 128>>>(H);                           // 1
    de_part_kernel<<<dim3(E_ / 256, 8, B_), 256>>>();                // 2 (reads g_H_hi)
    xt_kernel<<<dim3(N_ / 32, C_ / 32, B_), dim3(32, 8)>>>(x);       // 3
    gemm_tc<0><<<dim3(E_ / 128, B_), 512, DSMEM>>>(nullptr, nullptr);     // 4 <- profiled
    wsplit_kernel<<<(C_ * C_) / 256, 256>>>(W);                      // 5
    gemm_tc<1><<<dim3(N_ / 128, B_), 512, DSMEM>>>(nullptr, nullptr);     // 6
    gemm_tc<2><<<(B_ * N_) / 128, 512, DSMEM>>>(bias, out);          // 7
}